// round 12
// baseline (speedup 1.0000x reference)
#include <cuda_runtime.h>
#include <cuda_fp16.h>
#include <cstdint>

#define T_STEPS 64
#define B_DIM   32
#define W_DIM   1024
#define L_DIM   4
#define G_DIM   4096
#define NB      128
#define NT      512
#define KCH     128
#define NCH     16
#define ROWH    136

#define B_ST_BYTES (32 * ROWH * 2)          // 8704 per stage
#define RED_OFF    (4 * B_ST_BYTES)         // 34816
#define RED_BYTES  (2 * 128 * 36 * 4)       // 36864
#define DYN_BYTES  (RED_OFF + RED_BYTES)    // 71680

// weights in MMA-fragment order: [z=(wsel*4+l)*32+lcta][mtile 8][kstep 64][lane 32] x uint4
__device__ uint4  g_Wfrag[256 * 8 * 64 * 32];        // 67 MB
__device__ __half g_x16[T_STEPS][B_DIM][W_DIM];
__device__ __half g_hy[L_DIM][T_STEPS][B_DIM][W_DIM];     // unmasked h per (l,t)
__device__ __half g_hm[L_DIM][T_STEPS + 1][B_DIM][W_DIM]; // pre-masked recurrent, slot t
__device__ float  g_c[L_DIM][B_DIM][W_DIM];
__device__ unsigned g_done[L_DIM][T_STEPS];
__device__ unsigned g_count = 0;
__device__ unsigned g_gen   = 0;

static __device__ __forceinline__ unsigned smem_u32(const void* p) {
    return (unsigned)__cvta_generic_to_shared(p);
}

__device__ __forceinline__ void gridBarrier() {
    __syncthreads();
    if (threadIdx.x == 0) {
        volatile unsigned* genp = &g_gen;
        unsigned my = *genp;
        __threadfence();
        unsigned arrived = atomicAdd(&g_count, 1);
        if (arrived == NB - 1) {
            atomicExch(&g_count, 0);
            __threadfence();
            *genp = my + 1;
        } else {
            while (*genp == my) { }
        }
        __threadfence();
    }
    __syncthreads();
}

__device__ __forceinline__ void cpa16(unsigned dst, const void* src) {
    asm volatile("cp.async.cg.shared.global [%0], [%1], 16;" :: "r"(dst), "l"(src));
}
#define CP_COMMIT() asm volatile("cp.async.commit_group;" ::: "memory")

#define LDSM4(r0, r1, r2, r3, addr) \
    asm volatile("ldmatrix.sync.aligned.m8n8.x4.shared.b16 {%0,%1,%2,%3}, [%4];" \
                 : "=r"(r0), "=r"(r1), "=r"(r2), "=r"(r3) : "r"(addr))

__device__ __forceinline__ void mma_f16(float& c0, float& c1, float& c2, float& c3,
                                        unsigned a0, unsigned a1, unsigned a2, unsigned a3,
                                        unsigned b0, unsigned b1) {
    asm volatile(
        "mma.sync.aligned.m16n8k16.row.col.f32.f16.f16.f32 "
        "{%0,%1,%2,%3}, {%4,%5,%6,%7}, {%8,%9}, {%0,%1,%2,%3};"
        : "+f"(c0), "+f"(c1), "+f"(c2), "+f"(c3)
        : "r"(a0), "r"(a1), "r"(a2), "r"(a3), "r"(b0), "r"(b1));
}

__device__ __forceinline__ float fast_sigmoid(float v) {
    return 1.0f / (1.0f + __expf(-v));
}
__device__ __forceinline__ float fast_tanh(float v) {
    float e = __expf(-2.0f * v);
    return (1.0f - e) / (1.0f + e);
}

// ---------------- one-time converts ----------------
__global__ void convert_wfrag_kernel(const float* __restrict__ Wx, const float* __restrict__ Wh) {
    __shared__ float sm[128][17];
    const int kg    = blockIdx.x;
    const int mtile = blockIdx.y;
    const int z     = blockIdx.z;
    const int wsel  = z >> 7;
    const int l     = (z >> 5) & 3;
    const int lcta  = z & 31;
    const float* src = (wsel ? Wh : Wx) + (size_t)l * W_DIM * G_DIM;
    const int col_base = (mtile >> 1) * W_DIM + lcta * 32 + (mtile & 1) * 16;
    const int kbase = kg * 128;
    const int tid = threadIdx.x;

    const int cc = tid & 15, krow = tid >> 4;
    #pragma unroll
    for (int rep = 0; rep < 8; ++rep) {
        int k = krow + rep * 16;
        sm[k][cc] = src[(size_t)(kbase + k) * G_DIM + col_base + cc];
    }
    __syncthreads();

    const int ksl = tid >> 5, lane = tid & 31;
    const int r = lane >> 2, c2 = (lane & 3) * 2;
    const int kl = ksl * 16 + c2;
    unsigned short h[8];
    h[0] = __half_as_ushort(__float2half(sm[kl    ][r]));
    h[1] = __half_as_ushort(__float2half(sm[kl + 1][r]));
    h[2] = __half_as_ushort(__float2half(sm[kl    ][r + 8]));
    h[3] = __half_as_ushort(__float2half(sm[kl + 1][r + 8]));
    h[4] = __half_as_ushort(__float2half(sm[kl + 8][r]));
    h[5] = __half_as_ushort(__float2half(sm[kl + 9][r]));
    h[6] = __half_as_ushort(__float2half(sm[kl + 8][r + 8]));
    h[7] = __half_as_ushort(__float2half(sm[kl + 9][r + 8]));
    uint4 q;
    q.x = (unsigned)h[0] | ((unsigned)h[1] << 16);
    q.y = (unsigned)h[2] | ((unsigned)h[3] << 16);
    q.z = (unsigned)h[4] | ((unsigned)h[5] << 16);
    q.w = (unsigned)h[6] | ((unsigned)h[7] << 16);
    g_Wfrag[(((size_t)z * 8 + mtile) * 64 + kg * 8 + ksl) * 32 + lane] = q;
}

__global__ void convert_x_kernel(const float* __restrict__ x) {
    __half* dst = &g_x16[0][0][0];
    int i = blockIdx.x * blockDim.x + threadIdx.x;
    if (i < L_DIM * T_STEPS) (&g_done[0][0])[i] = 0;     // reset flags EVERY launch
    #pragma unroll
    for (int r = 0; r < 8; ++r) {
        int idx = i + r * (gridDim.x * blockDim.x);
        if (idx < T_STEPS * B_DIM * W_DIM) dst[idx] = __float2half(x[idx]);
    }
}

__global__ __launch_bounds__(NT) void lstm_mma_kernel(
    const void*  __restrict__ resets_raw,
    const float* __restrict__ c0,
    const float* __restrict__ h0,
    const float* __restrict__ bias,
    float* __restrict__ out)
{
    extern __shared__ __align__(16) char pool[];
    __shared__ float mask_next[B_DIM];
    __shared__ int s_rmode;

    const int tid  = threadIdx.x;
    const int cta  = blockIdx.x;
    const int lane = tid & 31;
    const int w    = tid >> 5;        // 0..15
    const int grp  = cta >> 5;        // layer owned
    const int lcta = cta & 31;
    const int u0   = lcta * 32;
    const int ms   = w & 7;           // M-slice 0..7 (one m16 tile)
    const int ks   = w >> 3;          // K-slice 0..1 (64 halfs)

    float* out_ys = out;
    float* out_cs = out + (size_t)T_STEPS * B_DIM * W_DIM;
    float* out_hs = out_cs + (size_t)L_DIM * B_DIM * W_DIM;

    if (tid == 0) {
        const unsigned char* rb = (const unsigned char*)resets_raw;
        int s1 = 0, s2 = 0, s3 = 0;
        for (int i = 0; i < T_STEPS * B_DIM; i += 4) { s1 += rb[i+1]; s2 += rb[i+2]; s3 += rb[i+3]; }
        s_rmode = (s1 > 0) ? 0 : ((s2 == 0 && s3 == 0) ? 1 : 2);
    }
    __syncthreads();
    const int rmode = s_rmode;

    const unsigned char* r8  = (const unsigned char*)resets_raw;
    const int*           r32 = (const int*)resets_raw;
    const float*         rf  = (const float*)resets_raw;
    #define KEEP(t, b) (rmode == 0 ? (r8[(t)*B_DIM+(b)] ? 0.0f : 1.0f) \
                      : rmode == 1 ? (r32[(t)*B_DIM+(b)] ? 0.0f : 1.0f) \
                                   : (rf[(t)*B_DIM+(b)] != 0.0f ? 0.0f : 1.0f))

    // ---- init: hm slot 0 = keep[0]*h0, c pre-masked ----
    for (int i = cta * NT + tid; i < L_DIM * B_DIM * W_DIM; i += NB * NT) {
        int b = (i >> 10) & 31;
        int l = i >> 15;
        float k0f = KEEP(0, b);
        (&g_hm[l][0][0][0])[i & 0x7FFF] = __float2half(k0f * h0[i]);
        (&g_c[0][0][0])[i]              = k0f * c0[i];
    }
    gridBarrier();   // one-time: init + flag reset visible everywhere

    const unsigned poolAddr = smem_u32(pool);
    float* red = (float*)(pool + RED_OFF);
    #define RED_IDX(kk, m, n) (((kk) * 128 + (m)) * 36 + (n))

    // ---- weight fragment bases ----
    const uint4* wbX = g_Wfrag + (((size_t)(0 * 4 + grp) * 32 + lcta) * 8) * 64 * 32;
    const uint4* wbH = g_Wfrag + (((size_t)(1 * 4 + grp) * 32 + lcta) * 8) * 64 * 32;
    // per-chunk A fragments: 4 k16-steps (this warp's k-slice)
    unsigned fidx[4];
    #pragma unroll
    for (int s = 0; s < 4; ++s)
        fidx[s] = (unsigned)((ms * 64 + ks * 4 + s) * 32 + lane);

    // ---- B staging ----
    const int bn  = tid >> 4;
    const int bkq = tid & 15;
    const unsigned bDst = (unsigned)((bn * ROWH + bkq * 8) * 2);
    const unsigned bSrc = (unsigned)(bn * W_DIM + bkq * 8);

    // ---- B ldmatrix offsets ----
    const int lrow8 = lane & 7;
    unsigned bRow[2];
    #pragma unroll
    for (int nt2 = 0; nt2 < 2; ++nt2)
        bRow[nt2] = (unsigned)((nt2 * 16 + lrow8 + ((lane >> 4) & 1) * 8) * ROWH * 2);
    const unsigned bKadj = (unsigned)(((lane >> 3) & 1) * 8 * 2);
    const unsigned kBase = (unsigned)(ks * 64 * 2);

    const int row = lane >> 2;
    const int kc2 = (lane & 3) * 2;

    // ---- cached per-thread epilogue constants ----
    const int uE  = tid & 31;           // unit within CTA
    const int npE = tid >> 5;           // 0..15
    const int ugE = u0 + uE;
    float bias_r[4];
    #pragma unroll
    for (int g = 0; g < 4; ++g)
        bias_r[g] = bias[grp * G_DIM + g * W_DIM + ugE];

    volatile unsigned* doneFlat = (volatile unsigned*)&g_done[0][0];

    for (int t = 0; t < T_STEPS; ++t) {
        // ---- wait for producers (usually already satisfied) ----
        if (tid == 0) {
            if (grp > 0) while (doneFlat[(grp - 1) * T_STEPS + t] < 32u) { }
            if (t > 0)   while (doneFlat[grp * T_STEPS + (t - 1)] < 32u) { }
            __threadfence();
        }
        __syncthreads();

        if (tid < B_DIM)
            mask_next[tid] = (t + 1 < T_STEPS) ? KEEP(t + 1, tid) : 1.0f;

        const __half* ax = (grp == 0) ? &g_x16[t][0][0] : &g_hy[grp - 1][t][0][0];
        const __half* ah = &g_hm[grp][t][0][0];

        // prologue: stage B chunks 0..2
        cpa16(poolAddr + 0 * B_ST_BYTES + bDst, ax + bSrc);           CP_COMMIT();
        cpa16(poolAddr + 1 * B_ST_BYTES + bDst, ax + bSrc + KCH);     CP_COMMIT();
        cpa16(poolAddr + 2 * B_ST_BYTES + bDst, ax + bSrc + 2 * KCH); CP_COMMIT();

        // prologue: A fragments chunk 0
        uint4 afrag[2][4];
        #pragma unroll
        for (int s = 0; s < 4; ++s)
            afrag[0][s] = wbX[fidx[s]];

        float acc[4][4];
        #pragma unroll
        for (int nt = 0; nt < 4; ++nt)
            #pragma unroll
            for (int q = 0; q < 4; ++q) acc[nt][q] = 0.0f;

        for (int c = 0; c < NCH; ++c) {
            if (c + 1 < NCH) {
                const int cn = c + 1;
                const uint4* wb = (cn < 8) ? wbX : wbH;
                const unsigned co = (unsigned)((cn & 7) * 256);
                #pragma unroll
                for (int s = 0; s < 4; ++s)
                    afrag[cn & 1][s] = wb[co + fidx[s]];
            }

            if (c <= NCH - 3)      asm volatile("cp.async.wait_group 2;" ::: "memory");
            else if (c == NCH - 2) asm volatile("cp.async.wait_group 1;" ::: "memory");
            else                   asm volatile("cp.async.wait_group 0;" ::: "memory");
            __syncthreads();

            if (c + 3 < NCH) {
                const int cn = c + 3;
                const __half* ab = (cn < 8) ? ax : ah;
                cpa16(poolAddr + (cn & 3) * B_ST_BYTES + bDst,
                      ab + bSrc + (cn & 7) * KCH);
                CP_COMMIT();
            }

            // ---- compute chunk c: 4 k16-steps ----
            const unsigned bsb = poolAddr + (c & 3) * B_ST_BYTES;
            #pragma unroll
            for (int s = 0; s < 4; ++s) {
                const unsigned kOff = kBase + (unsigned)(s * 16 * 2);
                unsigned b0[4], b1[4];
                LDSM4(b0[0], b0[1], b0[2], b0[3], bsb + bRow[0] + kOff + bKadj);
                LDSM4(b1[0], b1[1], b1[2], b1[3], bsb + bRow[1] + kOff + bKadj);
                const uint4 q = afrag[c & 1][s];
                mma_f16(acc[0][0], acc[0][1], acc[0][2], acc[0][3],
                        q.x, q.y, q.z, q.w, b0[0], b0[1]);
                mma_f16(acc[1][0], acc[1][1], acc[1][2], acc[1][3],
                        q.x, q.y, q.z, q.w, b0[2], b0[3]);
                mma_f16(acc[2][0], acc[2][1], acc[2][2], acc[2][3],
                        q.x, q.y, q.z, q.w, b1[0], b1[1]);
                mma_f16(acc[3][0], acc[3][1], acc[3][2], acc[3][3],
                        q.x, q.y, q.z, q.w, b1[2], b1[3]);
            }
        }

        // ---- k-slice partial exchange ----
        #pragma unroll
        for (int nt = 0; nt < 4; ++nt) {
            const int m_r = ms * 16 + row;
            const int n0  = nt * 8 + kc2;
            *(float2*)&red[RED_IDX(ks, m_r, n0)]     = make_float2(acc[nt][0], acc[nt][1]);
            *(float2*)&red[RED_IDX(ks, m_r + 8, n0)] = make_float2(acc[nt][2], acc[nt][3]);
        }
        __syncthreads();

        // ---- reduce + bias + LSTM pointwise (2 cells per thread) ----
        #pragma unroll
        for (int e = 0; e < 2; ++e) {
            const int n = npE * 2 + e;
            float gate[4];
            #pragma unroll
            for (int g = 0; g < 4; ++g) {
                const int m = g * 32 + uE;
                gate[g] = red[RED_IDX(0, m, n)] + red[RED_IDX(1, m, n)] + bias_r[g];
            }
            float cOld = g_c[grp][n][ugE];
            float cN = fast_sigmoid(gate[1]) * cOld + fast_sigmoid(gate[0]) * fast_tanh(gate[2]);
            float hN = fast_sigmoid(gate[3]) * fast_tanh(cN);
            float keepN = mask_next[n];

            g_c[grp][n][ugE] = keepN * cN;
            g_hy[grp][t][n][ugE]     = __float2half(hN);
            g_hm[grp][t + 1][n][ugE] = __float2half(keepN * hN);
            if (grp == L_DIM - 1)
                out_ys[((size_t)t * B_DIM + n) * W_DIM + ugE] = hN;
            if (t == T_STEPS - 1) {
                out_cs[((size_t)grp * B_DIM + n) * W_DIM + ugE] = cN;
                out_hs[((size_t)grp * B_DIM + n) * W_DIM + ugE] = hN;
            }
        }

        // ---- signal consumers ----
        __syncthreads();
        if (tid == 0) {
            __threadfence();
            atomicAdd((unsigned*)&g_done[grp][t], 1u);
        }
    }
    #undef KEEP
    #undef RED_IDX
}

extern "C" void kernel_launch(void* const* d_in, const int* in_sizes, int n_in,
                              void* d_out, int out_size) {
    const float* x      = (const float*)d_in[0];
    const void*  resets = (const void*) d_in[1];
    const float* c0     = (const float*)d_in[2];
    const float* h0     = (const float*)d_in[3];
    const float* Wx     = (const float*)d_in[4];
    const float* Wh     = (const float*)d_in[5];
    const float* b      = (const float*)d_in[6];
    (void)in_sizes; (void)n_in; (void)out_size;

    static int configured = 0;
    if (!configured) {
        cudaFuncSetAttribute(lstm_mma_kernel, cudaFuncAttributeMaxDynamicSharedMemorySize, DYN_BYTES);
        configured = 1;
    }

    convert_wfrag_kernel<<<dim3(8, 8, 256), 256>>>(Wx, Wh);
    convert_x_kernel<<<1024, 256>>>(x);
    lstm_mma_kernel<<<NB, NT, DYN_BYTES>>>(resets, c0, h0, b, (float*)d_out);
}

// round 13
// speedup vs baseline: 1.0608x; 1.0608x over previous
#include <cuda_runtime.h>
#include <cuda_fp16.h>
#include <cstdint>

#define T_STEPS 64
#define B_DIM   32
#define W_DIM   1024
#define L_DIM   4
#define G_DIM   4096
#define NB      128
#define NT      512
#define KCH     128
#define NCH     16
#define ROWH    136

#define B_ST_BYTES (32 * ROWH * 2)          // 8704 per stage
#define RED_OFF    (4 * B_ST_BYTES)         // 34816
#define RED_BYTES  (4 * 128 * 36 * 4)       // 73728
#define DYN_BYTES  (RED_OFF + RED_BYTES)    // 108544

// weights in MMA-fragment order: [z=(wsel*4+l)*32+lcta][mtile 8][kstep 64][lane 32] x uint4
__device__ uint4  g_Wfrag[256 * 8 * 64 * 32];        // 67 MB
__device__ __half g_x16[T_STEPS][B_DIM][W_DIM];
__device__ __half g_hy[L_DIM][T_STEPS][B_DIM][W_DIM];     // unmasked h per (l,t)
__device__ __half g_hm[L_DIM][T_STEPS + 1][B_DIM][W_DIM]; // pre-masked recurrent, slot t
__device__ float  g_c[L_DIM][B_DIM][W_DIM];
__device__ unsigned g_done[L_DIM][T_STEPS];
__device__ unsigned g_count = 0;
__device__ unsigned g_gen   = 0;

static __device__ __forceinline__ unsigned smem_u32(const void* p) {
    return (unsigned)__cvta_generic_to_shared(p);
}

__device__ __forceinline__ void gridBarrier() {
    __syncthreads();
    if (threadIdx.x == 0) {
        volatile unsigned* genp = &g_gen;
        unsigned my = *genp;
        __threadfence();
        unsigned arrived = atomicAdd(&g_count, 1);
        if (arrived == NB - 1) {
            atomicExch(&g_count, 0);
            __threadfence();
            *genp = my + 1;
        } else {
            while (*genp == my) { }
        }
        __threadfence();
    }
    __syncthreads();
}

__device__ __forceinline__ void cpa16(unsigned dst, const void* src) {
    asm volatile("cp.async.cg.shared.global [%0], [%1], 16;" :: "r"(dst), "l"(src));
}
#define CP_COMMIT() asm volatile("cp.async.commit_group;" ::: "memory")

#define LDSM4(r0, r1, r2, r3, addr) \
    asm volatile("ldmatrix.sync.aligned.m8n8.x4.shared.b16 {%0,%1,%2,%3}, [%4];" \
                 : "=r"(r0), "=r"(r1), "=r"(r2), "=r"(r3) : "r"(addr))

__device__ __forceinline__ void mma_f16(float& c0, float& c1, float& c2, float& c3,
                                        unsigned a0, unsigned a1, unsigned a2, unsigned a3,
                                        unsigned b0, unsigned b1) {
    asm volatile(
        "mma.sync.aligned.m16n8k16.row.col.f32.f16.f16.f32 "
        "{%0,%1,%2,%3}, {%4,%5,%6,%7}, {%8,%9}, {%0,%1,%2,%3};"
        : "+f"(c0), "+f"(c1), "+f"(c2), "+f"(c3)
        : "r"(a0), "r"(a1), "r"(a2), "r"(a3), "r"(b0), "r"(b1));
}

__device__ __forceinline__ float fast_sigmoid(float v) {
    return 1.0f / (1.0f + __expf(-v));
}
__device__ __forceinline__ float fast_tanh(float v) {
    float e = __expf(-2.0f * v);
    return (1.0f - e) / (1.0f + e);
}

// ---------------- one-time converts ----------------
__global__ void convert_wfrag_kernel(const float* __restrict__ Wx, const float* __restrict__ Wh) {
    __shared__ float sm[128][17];
    const int kg    = blockIdx.x;
    const int mtile = blockIdx.y;
    const int z     = blockIdx.z;
    const int wsel  = z >> 7;
    const int l     = (z >> 5) & 3;
    const int lcta  = z & 31;
    const float* src = (wsel ? Wh : Wx) + (size_t)l * W_DIM * G_DIM;
    const int col_base = (mtile >> 1) * W_DIM + lcta * 32 + (mtile & 1) * 16;
    const int kbase = kg * 128;
    const int tid = threadIdx.x;

    const int cc = tid & 15, krow = tid >> 4;
    #pragma unroll
    for (int rep = 0; rep < 8; ++rep) {
        int k = krow + rep * 16;
        sm[k][cc] = src[(size_t)(kbase + k) * G_DIM + col_base + cc];
    }
    __syncthreads();

    const int ksl = tid >> 5, lane = tid & 31;
    const int r = lane >> 2, c2 = (lane & 3) * 2;
    const int kl = ksl * 16 + c2;
    unsigned short h[8];
    h[0] = __half_as_ushort(__float2half(sm[kl    ][r]));
    h[1] = __half_as_ushort(__float2half(sm[kl + 1][r]));
    h[2] = __half_as_ushort(__float2half(sm[kl    ][r + 8]));
    h[3] = __half_as_ushort(__float2half(sm[kl + 1][r + 8]));
    h[4] = __half_as_ushort(__float2half(sm[kl + 8][r]));
    h[5] = __half_as_ushort(__float2half(sm[kl + 9][r]));
    h[6] = __half_as_ushort(__float2half(sm[kl + 8][r + 8]));
    h[7] = __half_as_ushort(__float2half(sm[kl + 9][r + 8]));
    uint4 q;
    q.x = (unsigned)h[0] | ((unsigned)h[1] << 16);
    q.y = (unsigned)h[2] | ((unsigned)h[3] << 16);
    q.z = (unsigned)h[4] | ((unsigned)h[5] << 16);
    q.w = (unsigned)h[6] | ((unsigned)h[7] << 16);
    g_Wfrag[(((size_t)z * 8 + mtile) * 64 + kg * 8 + ksl) * 32 + lane] = q;
}

__global__ void convert_x_kernel(const float* __restrict__ x) {
    __half* dst = &g_x16[0][0][0];
    int i = blockIdx.x * blockDim.x + threadIdx.x;
    if (i < L_DIM * T_STEPS) (&g_done[0][0])[i] = 0;     // reset flags EVERY launch
    #pragma unroll
    for (int r = 0; r < 8; ++r) {
        int idx = i + r * (gridDim.x * blockDim.x);
        if (idx < T_STEPS * B_DIM * W_DIM) dst[idx] = __float2half(x[idx]);
    }
}

__global__ __launch_bounds__(NT) void lstm_mma_kernel(
    const void*  __restrict__ resets_raw,
    const float* __restrict__ c0,
    const float* __restrict__ h0,
    const float* __restrict__ bias,
    float* __restrict__ out)
{
    extern __shared__ __align__(16) char pool[];
    __shared__ float mask_next[B_DIM];
    __shared__ int s_rmode;

    const int tid  = threadIdx.x;
    const int cta  = blockIdx.x;
    const int lane = tid & 31;
    const int w    = tid >> 5;        // 0..15
    const int grp  = cta >> 5;        // layer owned
    const int lcta = cta & 31;
    const int u0   = lcta * 32;
    const int ms   = w >> 2;          // M-slice 0..3
    const int ks   = w & 3;           // K-slice 0..3

    float* out_ys = out;
    float* out_cs = out + (size_t)T_STEPS * B_DIM * W_DIM;
    float* out_hs = out_cs + (size_t)L_DIM * B_DIM * W_DIM;

    if (tid == 0) {
        const unsigned char* rb = (const unsigned char*)resets_raw;
        int s1 = 0, s2 = 0, s3 = 0;
        for (int i = 0; i < T_STEPS * B_DIM; i += 4) { s1 += rb[i+1]; s2 += rb[i+2]; s3 += rb[i+3]; }
        s_rmode = (s1 > 0) ? 0 : ((s2 == 0 && s3 == 0) ? 1 : 2);
    }
    __syncthreads();
    const int rmode = s_rmode;

    const unsigned char* r8  = (const unsigned char*)resets_raw;
    const int*           r32 = (const int*)resets_raw;
    const float*         rf  = (const float*)resets_raw;
    #define KEEP(t, b) (rmode == 0 ? (r8[(t)*B_DIM+(b)] ? 0.0f : 1.0f) \
                      : rmode == 1 ? (r32[(t)*B_DIM+(b)] ? 0.0f : 1.0f) \
                                   : (rf[(t)*B_DIM+(b)] != 0.0f ? 0.0f : 1.0f))

    // ---- init: hm slot 0 = keep[0]*h0, c pre-masked ----
    for (int i = cta * NT + tid; i < L_DIM * B_DIM * W_DIM; i += NB * NT) {
        int b = (i >> 10) & 31;
        int l = i >> 15;
        float k0f = KEEP(0, b);
        (&g_hm[l][0][0][0])[i & 0x7FFF] = __float2half(k0f * h0[i]);
        (&g_c[0][0][0])[i]              = k0f * c0[i];
    }
    gridBarrier();   // one-time: init + flag reset visible everywhere

    const unsigned poolAddr = smem_u32(pool);
    float* red = (float*)(pool + RED_OFF);
    #define RED_IDX(kk, m, n) (((kk) * 128 + (m)) * 36 + (n))

    // ---- weight fragment bases ----
    const uint4* wbX = g_Wfrag + (((size_t)(0 * 4 + grp) * 32 + lcta) * 8) * 64 * 32;
    const uint4* wbH = g_Wfrag + (((size_t)(1 * 4 + grp) * 32 + lcta) * 8) * 64 * 32;
    unsigned fidx[2][2];
    #pragma unroll
    for (int mt = 0; mt < 2; ++mt)
        #pragma unroll
        for (int s = 0; s < 2; ++s)
            fidx[mt][s] = (unsigned)((((ms * 2 + mt) * 64) + ks * 2 + s) * 32 + lane);

    // ---- B staging ----
    const int bn  = tid >> 4;
    const int bkq = tid & 15;
    const unsigned bDst = (unsigned)((bn * ROWH + bkq * 8) * 2);
    const unsigned bSrc = (unsigned)(bn * W_DIM + bkq * 8);

    // ---- B ldmatrix offsets ----
    const int lrow8 = lane & 7;
    unsigned bRow[2];
    #pragma unroll
    for (int nt2 = 0; nt2 < 2; ++nt2)
        bRow[nt2] = (unsigned)((nt2 * 16 + lrow8 + ((lane >> 4) & 1) * 8) * ROWH * 2);
    const unsigned bKadj = (unsigned)(((lane >> 3) & 1) * 8 * 2);
    const unsigned kBase = (unsigned)(ks * 32 * 2);

    const int row = lane >> 2;
    const int kc2 = (lane & 3) * 2;

    // ---- cached per-thread epilogue constants ----
    const int uE  = tid & 31;
    const int npE = tid >> 5;
    const int ugE = u0 + uE;
    float bias_r[4];
    #pragma unroll
    for (int g = 0; g < 4; ++g)
        bias_r[g] = bias[grp * G_DIM + g * W_DIM + ugE];

    volatile unsigned* doneFlat = (volatile unsigned*)&g_done[0][0];

    for (int t = 0; t < T_STEPS; ++t) {
        // ---- wait for producers (usually already satisfied) ----
        if (tid == 0) {
            if (grp > 0) while (doneFlat[(grp - 1) * T_STEPS + t] < 32u) { }
            if (t > 0)   while (doneFlat[grp * T_STEPS + (t - 1)] < 32u) { }
            __threadfence();
        }
        __syncthreads();

        if (tid < B_DIM)
            mask_next[tid] = (t + 1 < T_STEPS) ? KEEP(t + 1, tid) : 1.0f;

        const __half* ax = (grp == 0) ? &g_x16[t][0][0] : &g_hy[grp - 1][t][0][0];
        const __half* ah = &g_hm[grp][t][0][0];

        // prologue: stage B chunks 0..2
        cpa16(poolAddr + 0 * B_ST_BYTES + bDst, ax + bSrc);           CP_COMMIT();
        cpa16(poolAddr + 1 * B_ST_BYTES + bDst, ax + bSrc + KCH);     CP_COMMIT();
        cpa16(poolAddr + 2 * B_ST_BYTES + bDst, ax + bSrc + 2 * KCH); CP_COMMIT();

        // prologue: A fragments chunk 0
        uint4 afrag[2][4];
        #pragma unroll
        for (int f = 0; f < 4; ++f)
            afrag[0][f] = wbX[fidx[f >> 1][f & 1]];

        float acc[2][4][4];
        #pragma unroll
        for (int mt = 0; mt < 2; ++mt)
            #pragma unroll
            for (int nt = 0; nt < 4; ++nt)
                #pragma unroll
                for (int q = 0; q < 4; ++q) acc[mt][nt][q] = 0.0f;

        for (int c = 0; c < NCH; ++c) {
            if (c + 1 < NCH) {
                const int cn = c + 1;
                const uint4* wb = (cn < 8) ? wbX : wbH;
                const unsigned co = (unsigned)((cn & 7) * 256);
                #pragma unroll
                for (int f = 0; f < 4; ++f)
                    afrag[cn & 1][f] = wb[co + fidx[f >> 1][f & 1]];
            }

            if (c <= NCH - 3)      asm volatile("cp.async.wait_group 2;" ::: "memory");
            else if (c == NCH - 2) asm volatile("cp.async.wait_group 1;" ::: "memory");
            else                   asm volatile("cp.async.wait_group 0;" ::: "memory");
            __syncthreads();

            if (c + 3 < NCH) {
                const int cn = c + 3;
                const __half* ab = (cn < 8) ? ax : ah;
                cpa16(poolAddr + (cn & 3) * B_ST_BYTES + bDst,
                      ab + bSrc + (cn & 7) * KCH);
                CP_COMMIT();
            }

            const unsigned bsb = poolAddr + (c & 3) * B_ST_BYTES;
            #pragma unroll
            for (int s = 0; s < 2; ++s) {
                const unsigned kOff = kBase + (unsigned)(s * 16 * 2);
                unsigned b0[4], b1[4];
                LDSM4(b0[0], b0[1], b0[2], b0[3], bsb + bRow[0] + kOff + bKadj);
                LDSM4(b1[0], b1[1], b1[2], b1[3], bsb + bRow[1] + kOff + bKadj);
                #pragma unroll
                for (int mt = 0; mt < 2; ++mt) {
                    const uint4 q = afrag[c & 1][mt * 2 + s];
                    mma_f16(acc[mt][0][0], acc[mt][0][1], acc[mt][0][2], acc[mt][0][3],
                            q.x, q.y, q.z, q.w, b0[0], b0[1]);
                    mma_f16(acc[mt][1][0], acc[mt][1][1], acc[mt][1][2], acc[mt][1][3],
                            q.x, q.y, q.z, q.w, b0[2], b0[3]);
                    mma_f16(acc[mt][2][0], acc[mt][2][1], acc[mt][2][2], acc[mt][2][3],
                            q.x, q.y, q.z, q.w, b1[0], b1[1]);
                    mma_f16(acc[mt][3][0], acc[mt][3][1], acc[mt][3][2], acc[mt][3][3],
                            q.x, q.y, q.z, q.w, b1[2], b1[3]);
                }
            }
        }

        // ---- k-slice partial exchange ----
        #pragma unroll
        for (int mt = 0; mt < 2; ++mt)
            #pragma unroll
            for (int nt = 0; nt < 4; ++nt) {
                const int m_r = ms * 32 + mt * 16 + row;
                const int n0  = nt * 8 + kc2;
                *(float2*)&red[RED_IDX(ks, m_r, n0)] =
                    make_float2(acc[mt][nt][0], acc[mt][nt][1]);
                *(float2*)&red[RED_IDX(ks, m_r + 8, n0)] =
                    make_float2(acc[mt][nt][2], acc[mt][nt][3]);
            }
        __syncthreads();

        // ---- reduce + bias + LSTM pointwise (2 cells per thread) ----
        #pragma unroll
        for (int e = 0; e < 2; ++e) {
            const int n = npE * 2 + e;
            float gate[4];
            #pragma unroll
            for (int g = 0; g < 4; ++g) {
                const int m = g * 32 + uE;
                gate[g] = red[RED_IDX(0, m, n)] + red[RED_IDX(1, m, n)]
                        + red[RED_IDX(2, m, n)] + red[RED_IDX(3, m, n)]
                        + bias_r[g];
            }
            float cOld = g_c[grp][n][ugE];
            float cN = fast_sigmoid(gate[1]) * cOld + fast_sigmoid(gate[0]) * fast_tanh(gate[2]);
            float hN = fast_sigmoid(gate[3]) * fast_tanh(cN);
            float keepN = mask_next[n];

            g_c[grp][n][ugE] = keepN * cN;
            g_hy[grp][t][n][ugE]     = __float2half(hN);
            g_hm[grp][t + 1][n][ugE] = __float2half(keepN * hN);
            if (grp == L_DIM - 1)
                out_ys[((size_t)t * B_DIM + n) * W_DIM + ugE] = hN;
            if (t == T_STEPS - 1) {
                out_cs[((size_t)grp * B_DIM + n) * W_DIM + ugE] = cN;
                out_hs[((size_t)grp * B_DIM + n) * W_DIM + ugE] = hN;
            }
        }

        // ---- signal consumers ----
        __syncthreads();
        if (tid == 0) {
            __threadfence();
            atomicAdd((unsigned*)&g_done[grp][t], 1u);
        }
    }
    #undef KEEP
    #undef RED_IDX
}

extern "C" void kernel_launch(void* const* d_in, const int* in_sizes, int n_in,
                              void* d_out, int out_size) {
    const float* x      = (const float*)d_in[0];
    const void*  resets = (const void*) d_in[1];
    const float* c0     = (const float*)d_in[2];
    const float* h0     = (const float*)d_in[3];
    const float* Wx     = (const float*)d_in[4];
    const float* Wh     = (const float*)d_in[5];
    const float* b      = (const float*)d_in[6];
    (void)in_sizes; (void)n_in; (void)out_size;

    static int configured = 0;
    if (!configured) {
        cudaFuncSetAttribute(lstm_mma_kernel, cudaFuncAttributeMaxDynamicSharedMemorySize, DYN_BYTES);
        configured = 1;
    }

    convert_wfrag_kernel<<<dim3(8, 8, 256), 256>>>(Wx, Wh);
    convert_x_kernel<<<1024, 256>>>(x);
    lstm_mma_kernel<<<NB, NT, DYN_BYTES>>>(resets, c0, h0, b, (float*)d_out);
}

// round 14
// speedup vs baseline: 1.0650x; 1.0040x over previous
#include <cuda_runtime.h>
#include <cuda_fp16.h>
#include <cstdint>

#define T_STEPS 64
#define B_DIM   32
#define W_DIM   1024
#define L_DIM   4
#define G_DIM   4096
#define NB      128
#define NT      512
#define KCH     256
#define NCH     8
#define ROWH    264          // 256 + 8 pad halfs

#define B_ST_BYTES (32 * ROWH * 2)          // 16896 per stage
#define RED_OFF    (4 * B_ST_BYTES)         // 67584
#define RED_BYTES  (4 * 128 * 36 * 4)       // 73728
#define DYN_BYTES  (RED_OFF + RED_BYTES)    // 141312

// weights in MMA-fragment order: [z=(wsel*4+l)*32+lcta][mtile 8][kstep 64][lane 32] x uint4
__device__ uint4  g_Wfrag[256 * 8 * 64 * 32];        // 67 MB
__device__ __half g_x16[T_STEPS][B_DIM][W_DIM];
__device__ __half g_hy[L_DIM][T_STEPS][B_DIM][W_DIM];     // unmasked h per (l,t)
__device__ __half g_hm[L_DIM][T_STEPS + 1][B_DIM][W_DIM]; // pre-masked recurrent, slot t
__device__ float  g_c[L_DIM][B_DIM][W_DIM];
__device__ unsigned g_done[L_DIM][T_STEPS];
__device__ unsigned g_count = 0;
__device__ unsigned g_gen   = 0;

static __device__ __forceinline__ unsigned smem_u32(const void* p) {
    return (unsigned)__cvta_generic_to_shared(p);
}

__device__ __forceinline__ void gridBarrier() {
    __syncthreads();
    if (threadIdx.x == 0) {
        volatile unsigned* genp = &g_gen;
        unsigned my = *genp;
        __threadfence();
        unsigned arrived = atomicAdd(&g_count, 1);
        if (arrived == NB - 1) {
            atomicExch(&g_count, 0);
            __threadfence();
            *genp = my + 1;
        } else {
            while (*genp == my) { }
        }
        __threadfence();
    }
    __syncthreads();
}

__device__ __forceinline__ void cpa16(unsigned dst, const void* src) {
    asm volatile("cp.async.cg.shared.global [%0], [%1], 16;" :: "r"(dst), "l"(src));
}
#define CP_COMMIT() asm volatile("cp.async.commit_group;" ::: "memory")

#define LDSM4(r0, r1, r2, r3, addr) \
    asm volatile("ldmatrix.sync.aligned.m8n8.x4.shared.b16 {%0,%1,%2,%3}, [%4];" \
                 : "=r"(r0), "=r"(r1), "=r"(r2), "=r"(r3) : "r"(addr))

__device__ __forceinline__ void mma_f16(float& c0, float& c1, float& c2, float& c3,
                                        unsigned a0, unsigned a1, unsigned a2, unsigned a3,
                                        unsigned b0, unsigned b1) {
    asm volatile(
        "mma.sync.aligned.m16n8k16.row.col.f32.f16.f16.f32 "
        "{%0,%1,%2,%3}, {%4,%5,%6,%7}, {%8,%9}, {%0,%1,%2,%3};"
        : "+f"(c0), "+f"(c1), "+f"(c2), "+f"(c3)
        : "r"(a0), "r"(a1), "r"(a2), "r"(a3), "r"(b0), "r"(b1));
}

__device__ __forceinline__ float sigmoidf_(float v) { return 1.0f / (1.0f + expf(-v)); }

// ---------------- one-time converts ----------------
__global__ void convert_wfrag_kernel(const float* __restrict__ Wx, const float* __restrict__ Wh) {
    __shared__ float sm[128][17];
    const int kg    = blockIdx.x;
    const int mtile = blockIdx.y;
    const int z     = blockIdx.z;
    const int wsel  = z >> 7;
    const int l     = (z >> 5) & 3;
    const int lcta  = z & 31;
    const float* src = (wsel ? Wh : Wx) + (size_t)l * W_DIM * G_DIM;
    const int col_base = (mtile >> 1) * W_DIM + lcta * 32 + (mtile & 1) * 16;
    const int kbase = kg * 128;
    const int tid = threadIdx.x;

    const int cc = tid & 15, krow = tid >> 4;
    #pragma unroll
    for (int rep = 0; rep < 8; ++rep) {
        int k = krow + rep * 16;
        sm[k][cc] = src[(size_t)(kbase + k) * G_DIM + col_base + cc];
    }
    __syncthreads();

    const int ksl = tid >> 5, lane = tid & 31;
    const int r = lane >> 2, c2 = (lane & 3) * 2;
    const int kl = ksl * 16 + c2;
    unsigned short h[8];
    h[0] = __half_as_ushort(__float2half(sm[kl    ][r]));
    h[1] = __half_as_ushort(__float2half(sm[kl + 1][r]));
    h[2] = __half_as_ushort(__float2half(sm[kl    ][r + 8]));
    h[3] = __half_as_ushort(__float2half(sm[kl + 1][r + 8]));
    h[4] = __half_as_ushort(__float2half(sm[kl + 8][r]));
    h[5] = __half_as_ushort(__float2half(sm[kl + 9][r]));
    h[6] = __half_as_ushort(__float2half(sm[kl + 8][r + 8]));
    h[7] = __half_as_ushort(__float2half(sm[kl + 9][r + 8]));
    uint4 q;
    q.x = (unsigned)h[0] | ((unsigned)h[1] << 16);
    q.y = (unsigned)h[2] | ((unsigned)h[3] << 16);
    q.z = (unsigned)h[4] | ((unsigned)h[5] << 16);
    q.w = (unsigned)h[6] | ((unsigned)h[7] << 16);
    g_Wfrag[(((size_t)z * 8 + mtile) * 64 + kg * 8 + ksl) * 32 + lane] = q;
}

__global__ void convert_x_kernel(const float* __restrict__ x) {
    __half* dst = &g_x16[0][0][0];
    int i = blockIdx.x * blockDim.x + threadIdx.x;
    if (i < L_DIM * T_STEPS) (&g_done[0][0])[i] = 0;     // reset flags EVERY launch
    #pragma unroll
    for (int r = 0; r < 8; ++r) {
        int idx = i + r * (gridDim.x * blockDim.x);
        if (idx < T_STEPS * B_DIM * W_DIM) dst[idx] = __float2half(x[idx]);
    }
}

__global__ __launch_bounds__(NT) void lstm_mma_kernel(
    const void*  __restrict__ resets_raw,
    const float* __restrict__ c0,
    const float* __restrict__ h0,
    const float* __restrict__ bias,
    float* __restrict__ out)
{
    extern __shared__ __align__(16) char pool[];
    __shared__ float mask_next[B_DIM];
    __shared__ int s_rmode;

    const int tid  = threadIdx.x;
    const int cta  = blockIdx.x;
    const int lane = tid & 31;
    const int w    = tid >> 5;        // 0..15
    const int grp  = cta >> 5;        // layer owned
    const int lcta = cta & 31;
    const int u0   = lcta * 32;
    const int ms   = w >> 2;          // M-slice 0..3
    const int ks   = w & 3;           // K-slice 0..3 (64 halfs per chunk)

    float* out_ys = out;
    float* out_cs = out + (size_t)T_STEPS * B_DIM * W_DIM;
    float* out_hs = out_cs + (size_t)L_DIM * B_DIM * W_DIM;

    if (tid == 0) {
        const unsigned char* rb = (const unsigned char*)resets_raw;
        int s1 = 0, s2 = 0, s3 = 0;
        for (int i = 0; i < T_STEPS * B_DIM; i += 4) { s1 += rb[i+1]; s2 += rb[i+2]; s3 += rb[i+3]; }
        s_rmode = (s1 > 0) ? 0 : ((s2 == 0 && s3 == 0) ? 1 : 2);
    }
    __syncthreads();
    const int rmode = s_rmode;

    const unsigned char* r8  = (const unsigned char*)resets_raw;
    const int*           r32 = (const int*)resets_raw;
    const float*         rf  = (const float*)resets_raw;
    #define KEEP(t, b) (rmode == 0 ? (r8[(t)*B_DIM+(b)] ? 0.0f : 1.0f) \
                      : rmode == 1 ? (r32[(t)*B_DIM+(b)] ? 0.0f : 1.0f) \
                                   : (rf[(t)*B_DIM+(b)] != 0.0f ? 0.0f : 1.0f))

    // ---- init: hm slot 0 = keep[0]*h0, c pre-masked ----
    for (int i = cta * NT + tid; i < L_DIM * B_DIM * W_DIM; i += NB * NT) {
        int b = (i >> 10) & 31;
        int l = i >> 15;
        float k0f = KEEP(0, b);
        (&g_hm[l][0][0][0])[i & 0x7FFF] = __float2half(k0f * h0[i]);
        (&g_c[0][0][0])[i]              = k0f * c0[i];
    }
    gridBarrier();   // one-time: init + flag reset visible everywhere

    const unsigned poolAddr = smem_u32(pool);
    float* red = (float*)(pool + RED_OFF);
    #define RED_IDX(kk, m, n) (((kk) * 128 + (m)) * 36 + (n))

    // ---- weight fragment bases ----
    const uint4* wbX = g_Wfrag + (((size_t)(0 * 4 + grp) * 32 + lcta) * 8) * 64 * 32;
    const uint4* wbH = g_Wfrag + (((size_t)(1 * 4 + grp) * 32 + lcta) * 8) * 64 * 32;
    // base index for (mt, sx): kstep base = ks*4; per half-chunk add ((c&3)*16 + h*2)*32
    unsigned fbase[2];
    #pragma unroll
    for (int mt = 0; mt < 2; ++mt)
        fbase[mt] = (unsigned)((((ms * 2 + mt) * 64) + ks * 4) * 32 + lane);

    // ---- B staging: 2 cpa16 per thread per chunk ----
    unsigned bDst[2], bSrc[2];
    #pragma unroll
    for (int i = 0; i < 2; ++i) {
        int o = tid + NT * i;              // 0..1023
        int n = o >> 5, kq = o & 31;
        bDst[i] = (unsigned)((n * ROWH + kq * 8) * 2);
        bSrc[i] = (unsigned)(n * W_DIM + kq * 8);
    }

    // ---- B ldmatrix offsets ----
    const int lrow8 = lane & 7;
    unsigned bRow[2];
    #pragma unroll
    for (int nt2 = 0; nt2 < 2; ++nt2)
        bRow[nt2] = (unsigned)((nt2 * 16 + lrow8 + ((lane >> 4) & 1) * 8) * ROWH * 2);
    const unsigned bKadj = (unsigned)(((lane >> 3) & 1) * 8 * 2);
    const unsigned kBase = (unsigned)(ks * 64 * 2);

    const int row = lane >> 2;
    const int kc2 = (lane & 3) * 2;

    const int uE  = tid & 31;
    const int npE = tid >> 5;
    const int ugE = u0 + uE;

    volatile unsigned* doneFlat = (volatile unsigned*)&g_done[0][0];

    for (int t = 0; t < T_STEPS; ++t) {
        // A fragments for half-chunk 0 — weights only, independent of producers
        uint4 afrag[2][4];
        #pragma unroll
        for (int mt = 0; mt < 2; ++mt)
            #pragma unroll
            for (int sx = 0; sx < 2; ++sx)
                afrag[0][mt * 2 + sx] = wbX[fbase[mt] + sx * 32];

        // ---- wait for producers (usually already satisfied) ----
        if (tid == 0) {
            if (grp > 0) while (doneFlat[(grp - 1) * T_STEPS + t] < 32u) { }
            if (t > 0)   while (doneFlat[grp * T_STEPS + (t - 1)] < 32u) { }
            __threadfence();
        }
        __syncthreads();

        if (tid < B_DIM)
            mask_next[tid] = (t + 1 < T_STEPS) ? KEEP(t + 1, tid) : 1.0f;

        const __half* ax = (grp == 0) ? &g_x16[t][0][0] : &g_hy[grp - 1][t][0][0];
        const __half* ah = &g_hm[grp][t][0][0];

        // prologue: stage B chunks 0..2
        #pragma unroll
        for (int pc = 0; pc < 3; ++pc) {
            cpa16(poolAddr + pc * B_ST_BYTES + bDst[0], ax + bSrc[0] + pc * KCH);
            cpa16(poolAddr + pc * B_ST_BYTES + bDst[1], ax + bSrc[1] + pc * KCH);
            CP_COMMIT();
        }

        float acc[2][4][4];
        #pragma unroll
        for (int mt = 0; mt < 2; ++mt)
            #pragma unroll
            for (int nt = 0; nt < 4; ++nt)
                #pragma unroll
                for (int q = 0; q < 4; ++q) acc[mt][nt][q] = 0.0f;

        for (int hc = 0; hc < 2 * NCH; ++hc) {
            const int c = hc >> 1, h = hc & 1;

            // prefetch A fragments for half-chunk hc+1
            if (hc + 1 < 2 * NCH) {
                const int hn = hc + 1;
                const int cn = hn >> 1;
                const uint4* wb = (cn < 4) ? wbX : wbH;
                const unsigned co = (unsigned)(((cn & 3) * 16 + (hn & 1) * 2) * 32);
                #pragma unroll
                for (int mt = 0; mt < 2; ++mt)
                    #pragma unroll
                    for (int sx = 0; sx < 2; ++sx)
                        afrag[hn & 1][mt * 2 + sx] = wb[fbase[mt] + co + sx * 32];
            }

            if (h == 0) {
                if (c <= NCH - 3)      asm volatile("cp.async.wait_group 2;" ::: "memory");
                else if (c == NCH - 2) asm volatile("cp.async.wait_group 1;" ::: "memory");
                else                   asm volatile("cp.async.wait_group 0;" ::: "memory");
                __syncthreads();

                if (c + 3 < NCH) {
                    const int cn = c + 3;
                    const __half* ab = (cn < 4) ? ax : ah;
                    const unsigned kc = (unsigned)((cn & 3) * KCH);
                    cpa16(poolAddr + (cn & 3) * B_ST_BYTES + bDst[0], ab + bSrc[0] + kc);
                    cpa16(poolAddr + (cn & 3) * B_ST_BYTES + bDst[1], ab + bSrc[1] + kc);
                    CP_COMMIT();
                }
            }

            // ---- compute half-chunk hc (2 k16-steps) ----
            const unsigned bsb = poolAddr + (c & 3) * B_ST_BYTES;
            #pragma unroll
            for (int sx = 0; sx < 2; ++sx) {
                const unsigned kOff = kBase + (unsigned)((h * 2 + sx) * 16 * 2);
                unsigned b0[4], b1[4];
                LDSM4(b0[0], b0[1], b0[2], b0[3], bsb + bRow[0] + kOff + bKadj);
                LDSM4(b1[0], b1[1], b1[2], b1[3], bsb + bRow[1] + kOff + bKadj);
                #pragma unroll
                for (int mt = 0; mt < 2; ++mt) {
                    const uint4 q = afrag[hc & 1][mt * 2 + sx];
                    mma_f16(acc[mt][0][0], acc[mt][0][1], acc[mt][0][2], acc[mt][0][3],
                            q.x, q.y, q.z, q.w, b0[0], b0[1]);
                    mma_f16(acc[mt][1][0], acc[mt][1][1], acc[mt][1][2], acc[mt][1][3],
                            q.x, q.y, q.z, q.w, b0[2], b0[3]);
                    mma_f16(acc[mt][2][0], acc[mt][2][1], acc[mt][2][2], acc[mt][2][3],
                            q.x, q.y, q.z, q.w, b1[0], b1[1]);
                    mma_f16(acc[mt][3][0], acc[mt][3][1], acc[mt][3][2], acc[mt][3][3],
                            q.x, q.y, q.z, q.w, b1[2], b1[3]);
                }
            }
        }

        // ---- k-slice partial exchange ----
        #pragma unroll
        for (int mt = 0; mt < 2; ++mt)
            #pragma unroll
            for (int nt = 0; nt < 4; ++nt) {
                const int m_r = ms * 32 + mt * 16 + row;
                const int n0  = nt * 8 + kc2;
                *(float2*)&red[RED_IDX(ks, m_r, n0)] =
                    make_float2(acc[mt][nt][0], acc[mt][nt][1]);
                *(float2*)&red[RED_IDX(ks, m_r + 8, n0)] =
                    make_float2(acc[mt][nt][2], acc[mt][nt][3]);
            }
        __syncthreads();

        // ---- reduce + bias + LSTM pointwise (2 cells per thread) ----
        #pragma unroll
        for (int e = 0; e < 2; ++e) {
            const int n = npE * 2 + e;
            float gate[4];
            #pragma unroll
            for (int g = 0; g < 4; ++g) {
                const int m = g * 32 + uE;
                gate[g] = red[RED_IDX(0, m, n)] + red[RED_IDX(1, m, n)]
                        + red[RED_IDX(2, m, n)] + red[RED_IDX(3, m, n)]
                        + bias[grp * G_DIM + g * W_DIM + ugE];
            }
            float cOld = g_c[grp][n][ugE];
            float cN = sigmoidf_(gate[1]) * cOld + sigmoidf_(gate[0]) * tanhf(gate[2]);
            float hN = sigmoidf_(gate[3]) * tanhf(cN);
            float keepN = mask_next[n];

            g_c[grp][n][ugE] = keepN * cN;
            g_hy[grp][t][n][ugE]     = __float2half(hN);
            g_hm[grp][t + 1][n][ugE] = __float2half(keepN * hN);
            if (grp == L_DIM - 1)
                out_ys[((size_t)t * B_DIM + n) * W_DIM + ugE] = hN;
            if (t == T_STEPS - 1) {
                out_cs[((size_t)grp * B_DIM + n) * W_DIM + ugE] = cN;
                out_hs[((size_t)grp * B_DIM + n) * W_DIM + ugE] = hN;
            }
        }

        // ---- signal consumers ----
        __syncthreads();
        if (tid == 0) {
            __threadfence();
            atomicAdd((unsigned*)&g_done[grp][t], 1u);
        }
    }
    #undef KEEP
    #undef RED_IDX
}

extern "C" void kernel_launch(void* const* d_in, const int* in_sizes, int n_in,
                              void* d_out, int out_size) {
    const float* x      = (const float*)d_in[0];
    const void*  resets = (const void*) d_in[1];
    const float* c0     = (const float*)d_in[2];
    const float* h0     = (const float*)d_in[3];
    const float* Wx     = (const float*)d_in[4];
    const float* Wh     = (const float*)d_in[5];
    const float* b      = (const float*)d_in[6];
    (void)in_sizes; (void)n_in; (void)out_size;

    static int configured = 0;
    if (!configured) {
        cudaFuncSetAttribute(lstm_mma_kernel, cudaFuncAttributeMaxDynamicSharedMemorySize, DYN_BYTES);
        configured = 1;
    }

    convert_wfrag_kernel<<<dim3(8, 8, 256), 256>>>(Wx, Wh);
    convert_x_kernel<<<1024, 256>>>(x);
    lstm_mma_kernel<<<NB, NT, DYN_BYTES>>>(resets, c0, h0, b, (float*)d_out);
}